// round 15
// baseline (speedup 1.0000x reference)
#include <cuda_runtime.h>
#include <cuda_bf16.h>
#include <cstdint>

// ---------------------------------------------------------------------------
// RNN Autoencoder (GRU enc/dec), B=512, T=180, H=256, LAT=128
//   32 blocks x 256 threads, 16 batch rows per block.
//   bf16 hi/lo split tensor-core GEMMs (3 mma products per tile).
//   h state kept PRE-SPLIT (bf16 hi/lo u32 arrays) in smem; fp32 h in regs.
//   B fragments software-pipelined (ping-pong register buffers).
// ---------------------------------------------------------------------------

#define T_LEN 180
#define HID   256
#define BT    16
#define HS    264               // fp32 h1 stride (floats)
#define HWU   136               // hi/lo row stride in u32 (128 + 8)
#define PACK_PER_MAT 196608     // 96 ntiles * 16 ktiles * 32 lanes * 4 u32
#define RECON_ELEMS  (512 * T_LEN * 2)   // 184320

__device__ __align__(16) unsigned g_pack[6 * PACK_PER_MAT]; // packed weights
__device__ float g_xn[512 * T_LEN * 2];                      // layernormed input
__device__ float g_fcdec[512 * 512];                         // fc_dec output flat

// ---------------------------------------------------------------------------
__device__ __forceinline__ float sigm(float x) {
    return __fdividef(1.f, 1.f + __expf(-x));
}
__device__ __forceinline__ float tanh_(float x) {
    float ax = fabsf(x);
    float e  = __expf(-2.f * ax);
    float t  = __fdividef(1.f - e, 1.f + e);
    return copysignf(t, x);
}

// split floats (x,y) into bf16 hi pair and bf16 residual-lo pair (packed bf16x2)
__device__ __forceinline__ void splitf2(float x, float y, unsigned& hi, unsigned& lo) {
    __nv_bfloat16 hx = __float2bfloat16(x);
    __nv_bfloat16 hy = __float2bfloat16(y);
    __nv_bfloat16 lx = __float2bfloat16(x - __bfloat162float(hx));
    __nv_bfloat16 ly = __float2bfloat16(y - __bfloat162float(hy));
    hi = ((unsigned)__bfloat16_as_ushort(hy) << 16) | (unsigned)__bfloat16_as_ushort(hx);
    lo = ((unsigned)__bfloat16_as_ushort(ly) << 16) | (unsigned)__bfloat16_as_ushort(lx);
}

__device__ __forceinline__ void mma16816(float* c, const unsigned* a, unsigned b0, unsigned b1) {
    asm volatile(
        "mma.sync.aligned.m16n8k16.row.col.f32.bf16.bf16.f32 "
        "{%0,%1,%2,%3},{%4,%5,%6,%7},{%8,%9},{%0,%1,%2,%3};\n"
        : "+f"(c[0]), "+f"(c[1]), "+f"(c[2]), "+f"(c[3])
        : "r"(a[0]), "r"(a[1]), "r"(a[2]), "r"(a[3]), "r"(b0), "r"(b1));
}

// hi/lo smem pair layout: pair-col c (0..127, covers h cols 2c,2c+1)
//   u32 addr(row,c) = row*HWU + (c>>3)*8 + (c&3)*2 + ((c>>2)&1)
// so gemm's A-frag pair (c0, c0+4) with c0 = 8*kt+q is two adjacent u32 -> LDS.64
__device__ __forceinline__ int pair_addr(int c) {
    return (c >> 3) * 8 + (c & 3) * 2 + ((c >> 2) & 1);
}

// ---------------------------------------------------------------------------
// pack: W (768x256 row-major) -> per-lane B-fragment order with hi/lo split.
//   u32 offset = m*PACK_PER_MAT + ntile*2048 + kt*128 + lane*4
// ---------------------------------------------------------------------------
__global__ void pack_kernel(const float* __restrict__ w0, const float* __restrict__ w1,
                            const float* __restrict__ w2, const float* __restrict__ w3,
                            const float* __restrict__ w4, const float* __restrict__ w5) {
    int tid = blockIdx.x * blockDim.x + threadIdx.x;
    if (tid >= 6 * 49152) return;
    int m   = tid / 49152;
    int rem = tid % 49152;
    int nt  = rem >> 9;
    int kt  = (rem >> 5) & 15;
    int t   = rem & 31;
    const float* W = (m == 0) ? w0 : (m == 1) ? w1 : (m == 2) ? w2
                   : (m == 3) ? w3 : (m == 4) ? w4 : w5;
    int n  = nt * 8 + (t >> 2);
    int k0 = kt * 16 + (t & 3) * 2;
    const float* row = W + n * HID;
    unsigned h0, l0, h1, l1;
    splitf2(row[k0],     row[k0 + 1], h0, l0);
    splitf2(row[k0 + 8], row[k0 + 9], h1, l1);
    unsigned* dst = g_pack + m * PACK_PER_MAT + (((nt * 16 + kt) * 32 + t) << 2);
    uint4 v; v.x = h0; v.y = h1; v.z = l0; v.w = l1;
    *(uint4*)dst = v;
}

// ---------------------------------------------------------------------------
__global__ void ln_kernel(const float* __restrict__ x, const float* __restrict__ lw,
                          const float* __restrict__ lb) {
    int b = blockIdx.x;
    const float* xb = x + b * 360;
    float s = 0.f, s2 = 0.f;
    for (int i = threadIdx.x; i < 360; i += blockDim.x) {
        float v = xb[i]; s += v; s2 += v * v;
    }
    __shared__ float sh[8];
    for (int o = 16; o; o >>= 1) {
        s  += __shfl_down_sync(0xffffffffu, s, o);
        s2 += __shfl_down_sync(0xffffffffu, s2, o);
    }
    int wid = threadIdx.x >> 5;
    if ((threadIdx.x & 31) == 0) { sh[wid] = s; sh[4 + wid] = s2; }
    __syncthreads();
    if (threadIdx.x == 0) {
        float ts = sh[0] + sh[1] + sh[2] + sh[3];
        float t2 = sh[4] + sh[5] + sh[6] + sh[7];
        float mu = ts * (1.f / 360.f);
        float var = t2 * (1.f / 360.f) - mu * mu;
        sh[0] = mu;
        sh[1] = rsqrtf(var + 1e-5f);
    }
    __syncthreads();
    float mu = sh[0], rstd = sh[1];
    for (int i = threadIdx.x; i < 360; i += blockDim.x)
        g_xn[b * 360 + i] = (xb[i] - mu) * rstd * lw[i] + lb[i];
}

// ---------------------------------------------------------------------------
// B-fragment loader + one k-tile of mma work
// ---------------------------------------------------------------------------
__device__ __forceinline__ void ldB(uint4* Bf, const unsigned* __restrict__ Pl, int kt) {
#pragma unroll
    for (int e = 0; e < 12; e++)
        Bf[e] = *(const uint4*)(Pl + kt * 128 + (unsigned)((e & 3) + (e >> 2) * 32) * 2048u);
}

__device__ __forceinline__ void do_kt(const uint4* Bf,
                                      const unsigned* __restrict__ hA, const unsigned* __restrict__ hB,
                                      const unsigned* __restrict__ lA, const unsigned* __restrict__ lB,
                                      int kt, int q,
                                      float Cr[4][4], float Cz[4][4], float Cn[4][4]) {
    unsigned ah[4], al[4];
    int off = kt * 8 + q * 2;
    uint2 t0 = *(const uint2*)(hA + off); ah[0] = t0.x; ah[2] = t0.y;
    uint2 t1 = *(const uint2*)(hB + off); ah[1] = t1.x; ah[3] = t1.y;
    uint2 t2 = *(const uint2*)(lA + off); al[0] = t2.x; al[2] = t2.y;
    uint2 t3 = *(const uint2*)(lB + off); al[1] = t3.x; al[3] = t3.y;
#pragma unroll
    for (int e = 0; e < 12; e++) {
        float* C = (e < 4) ? Cr[e] : (e < 8) ? Cz[e - 4] : Cn[e - 8];
        mma16816(C, ah, Bf[e].x, Bf[e].y);
    }
#pragma unroll
    for (int e = 0; e < 12; e++) {
        float* C = (e < 4) ? Cr[e] : (e < 8) ? Cz[e - 4] : Cn[e - 8];
        mma16816(C, ah, Bf[e].z, Bf[e].w);
    }
#pragma unroll
    for (int e = 0; e < 12; e++) {
        float* C = (e < 4) ? Cr[e] : (e < 8) ? Cz[e - 4] : Cn[e - 8];
        mma16816(C, al, Bf[e].x, Bf[e].y);
    }
}

// full 16x256 @ 256x768-slice GEMM accumulate, B double-buffered in registers
__device__ __forceinline__ void gemm_acc(const unsigned* __restrict__ hi,
                                         const unsigned* __restrict__ lo,
                                         const unsigned* __restrict__ P,
                                         float Cr[4][4], float Cz[4][4], float Cn[4][4],
                                         int w, int lane) {
    const int r0 = lane >> 2, q = lane & 3;
    const unsigned* hA = hi + r0 * HWU;
    const unsigned* hB = hi + (r0 + 8) * HWU;
    const unsigned* lA = lo + r0 * HWU;
    const unsigned* lB = lo + (r0 + 8) * HWU;
    const unsigned* Pl = P + lane * 4 + (unsigned)(w * 4) * 2048u;
    uint4 B0[12], B1[12];
    ldB(B0, Pl, 0);
#pragma unroll 1
    for (int m = 0; m < 8; m++) {
        ldB(B1, Pl, 2 * m + 1);
        do_kt(B0, hA, hB, lA, lB, 2 * m, q, Cr, Cz, Cn);
        if (m < 7) ldB(B0, Pl, 2 * m + 2);
        do_kt(B1, hA, hB, lA, lB, 2 * m + 1, q, Cr, Cz, Cn);
    }
}

// ---------------------------------------------------------------------------
__device__ __forceinline__ void init_gates(float Cr[4][4], float Cz[4][4],
                                           float Cin[4][4], float Chn[4][4],
                                           const float* __restrict__ bih,
                                           const float* __restrict__ bhh, int w, int q) {
#pragma unroll
    for (int j = 0; j < 4; j++) {
        int cb = 32 * w + 8 * j + 2 * q;
        float2 bi, bh;
        bi = *(const float2*)(bih + cb); bh = *(const float2*)(bhh + cb);
        Cr[j][0] = Cr[j][2] = bi.x + bh.x; Cr[j][1] = Cr[j][3] = bi.y + bh.y;
        bi = *(const float2*)(bih + 256 + cb); bh = *(const float2*)(bhh + 256 + cb);
        Cz[j][0] = Cz[j][2] = bi.x + bh.x; Cz[j][1] = Cz[j][3] = bi.y + bh.y;
        bi = *(const float2*)(bih + 512 + cb); bh = *(const float2*)(bhh + 512 + cb);
        Cin[j][0] = Cin[j][2] = bi.x; Cin[j][1] = Cin[j][3] = bi.y;
        Chn[j][0] = Chn[j][2] = bh.x; Chn[j][1] = Chn[j][3] = bh.y;
    }
}

// scalar ih path for 2-dim inputs: Wih is (768,2) row-major
__device__ __forceinline__ void add_x2(float Cr[4][4], float Cz[4][4], float Cin[4][4],
                                       const float* __restrict__ Wih,
                                       float xa0, float xa1, float xb0, float xb1,
                                       int w, int q) {
#pragma unroll
    for (int j = 0; j < 4; j++) {
        int cb = 32 * w + 8 * j + 2 * q;
#pragma unroll
        for (int g = 0; g < 3; g++) {
            float* C = (g == 0) ? Cr[j] : (g == 1) ? Cz[j] : Cin[j];
            int c0 = g * 256 + cb;
            float2 w0 = *(const float2*)(Wih + c0 * 2);
            float2 w1 = *(const float2*)(Wih + (c0 + 1) * 2);
            C[0] += xa0 * w0.x + xa1 * w0.y;
            C[1] += xa0 * w1.x + xa1 * w1.y;
            C[2] += xb0 * w0.x + xb1 * w0.y;
            C[3] += xb0 * w1.x + xb1 * w1.y;
        }
    }
}

// GRU gate combine: h_prev in regs, write new h to regs + hi/lo smem (+opt fp32)
__device__ __forceinline__ void combine_reg(float* __restrict__ hreg,
                                            unsigned* __restrict__ hi, unsigned* __restrict__ lo,
                                            float Cr[4][4], float Cz[4][4],
                                            float Cin[4][4], float Chn[4][4],
                                            int w, int r0, int q, float* __restrict__ f32s) {
#pragma unroll
    for (int j = 0; j < 4; j++) {
        int cb = 32 * w + 8 * j + 2 * q;
        float nh[4];
#pragma unroll
        for (int k = 0; k < 4; k++) {
            float rg = sigm(Cr[j][k]);
            float zg = sigm(Cz[j][k]);
            float ng = tanh_(Cin[j][k] + rg * Chn[j][k]);
            nh[k] = (1.f - zg) * ng + zg * hreg[j * 4 + k];
            hreg[j * 4 + k] = nh[k];
        }
        int ad = pair_addr(cb >> 1);
        unsigned hw, lw_;
        splitf2(nh[0], nh[1], hw, lw_);
        hi[r0 * HWU + ad] = hw; lo[r0 * HWU + ad] = lw_;
        splitf2(nh[2], nh[3], hw, lw_);
        hi[(r0 + 8) * HWU + ad] = hw; lo[(r0 + 8) * HWU + ad] = lw_;
        if (f32s) {
            *(float2*)(f32s + r0 * HS + cb)       = make_float2(nh[0], nh[1]);
            *(float2*)(f32s + (r0 + 8) * HS + cb) = make_float2(nh[2], nh[3]);
        }
    }
}

// ---------------------------------------------------------------------------
// encoder: 2-layer GRU scan + fc_enc (-> z output) + fc_dec (-> g_fcdec)
// dyn smem: h0hi(2176 u32) h0lo h1hi h1lo | h1f(4224 f) | zs(2112 f) = 60160B
// ---------------------------------------------------------------------------
__global__ void __launch_bounds__(256, 1) enc_kernel(
    const float* __restrict__ Wih0, const float* __restrict__ bih0,
    const float* __restrict__ bhh0, const float* __restrict__ bih1,
    const float* __restrict__ bhh1,
    const float* __restrict__ fce_w, const float* __restrict__ fce_b,
    const float* __restrict__ fcd_w, const float* __restrict__ fcd_b,
    float* __restrict__ out) {
    extern __shared__ unsigned dsm[];
    unsigned* h0hi = dsm;
    unsigned* h0lo = dsm + 2176;
    unsigned* h1hi = dsm + 4352;
    unsigned* h1lo = dsm + 6528;
    float* h1f = (float*)(dsm + 8704);
    float* zs  = h1f + 4224;

    const int tid = threadIdx.x;
    const int w = tid >> 5, lane = tid & 31;
    const int r0 = lane >> 2, q = lane & 3;
    const int bg = blockIdx.x * BT;

    for (int i = tid; i < 8704; i += 256) dsm[i] = 0;
    float hreg0[16], hreg1[16];
#pragma unroll
    for (int k = 0; k < 16; k++) { hreg0[k] = 0.f; hreg1[k] = 0.f; }
    __syncthreads();

    const unsigned* P0 = g_pack;                      // enc_Whh0
    const unsigned* P1 = g_pack + PACK_PER_MAT;       // enc_Wih1
    const unsigned* P2 = g_pack + 2 * PACK_PER_MAT;   // enc_Whh1

    for (int t = 0; t < T_LEN; t++) {
        float Cr[4][4], Cz[4][4], Cin[4][4], Chn[4][4];
        // ---- layer 0 ----
        init_gates(Cr, Cz, Cin, Chn, bih0, bhh0, w, q);
        {
            const float* xr = g_xn + (bg + r0) * 360 + t * 2;
            const float* xs = g_xn + (bg + r0 + 8) * 360 + t * 2;
            add_x2(Cr, Cz, Cin, Wih0, xr[0], xr[1], xs[0], xs[1], w, q);
        }
        gemm_acc(h0hi, h0lo, P0, Cr, Cz, Chn, w, lane);
        __syncthreads();
        combine_reg(hreg0, h0hi, h0lo, Cr, Cz, Cin, Chn, w, r0, q, nullptr);
        __syncthreads();
        // ---- layer 1 ----
        init_gates(Cr, Cz, Cin, Chn, bih1, bhh1, w, q);
        gemm_acc(h0hi, h0lo, P1, Cr, Cz, Cin, w, lane);  // ih side
        gemm_acc(h1hi, h1lo, P2, Cr, Cz, Chn, w, lane);  // hh side
        __syncthreads();
        combine_reg(hreg1, h1hi, h1lo, Cr, Cz, Cin, Chn, w, r0, q, h1f);
        __syncthreads();
    }

    // ---- fc_enc: z = tanh(h1 @ W^T + b) ; write z to output tail ----
    for (int o = tid; o < 16 * 128; o += 256) {
        int row = o >> 7, lat = o & 127;
        float sum = fce_b[lat];
        const float* wr = fce_w + lat * 256;
        const float* hr = h1f + row * HS;
        for (int k = 0; k < 256; k++) sum += hr[k] * wr[k];
        float zv = tanh_(sum);
        zs[row * 132 + lat] = zv;
        out[RECON_ELEMS + (bg + row) * 128 + lat] = zv;
    }
    __syncthreads();

    // ---- fc_dec: (16 x 128) @ (128 -> 512) -> g_fcdec flat ----
    for (int o = tid; o < 16 * 512; o += 256) {
        int row = o >> 9, c = o & 511;
        float sum = fcd_b[c];
        const float* wr = fcd_w + c * 128;
        const float* zr = zs + row * 132;
        for (int k = 0; k < 128; k++) sum += zr[k] * wr[k];
        g_fcdec[(bg + row) * 512 + c] = sum;
    }
}

// ---------------------------------------------------------------------------
// decoder: autoregressive 2-layer GRU + fc_out each step
// dyn smem: h0hi h0lo h1hi h1lo | h1f | ys(32 f) = 51840B
// ---------------------------------------------------------------------------
__global__ void __launch_bounds__(256, 1) dec_kernel(
    const float* __restrict__ Wih0, const float* __restrict__ bih0,
    const float* __restrict__ bhh0, const float* __restrict__ bih1,
    const float* __restrict__ bhh1,
    const float* __restrict__ fco_w, const float* __restrict__ fco_b,
    float* __restrict__ out) {
    extern __shared__ unsigned dsm[];
    unsigned* h0hi = dsm;
    unsigned* h0lo = dsm + 2176;
    unsigned* h1hi = dsm + 4352;
    unsigned* h1lo = dsm + 6528;
    float* h1f = (float*)(dsm + 8704);
    float* ys  = h1f + 4224;

    const int tid = threadIdx.x;
    const int w = tid >> 5, lane = tid & 31;
    const int r0 = lane >> 2, q = lane & 3;
    const int bg = blockIdx.x * BT;

    // init hidden state from g_fcdec via raw reshape(NL,B,H) view
    float hreg0[16], hreg1[16];
#pragma unroll
    for (int j = 0; j < 4; j++) {
        int cb = 32 * w + 8 * j + 2 * q;
        int ad = pair_addr(cb >> 1);
        float a0 = g_fcdec[(bg + r0) * 256 + cb];
        float a1 = g_fcdec[(bg + r0) * 256 + cb + 1];
        float a2 = g_fcdec[(bg + r0 + 8) * 256 + cb];
        float a3 = g_fcdec[(bg + r0 + 8) * 256 + cb + 1];
        hreg0[j * 4 + 0] = a0; hreg0[j * 4 + 1] = a1;
        hreg0[j * 4 + 2] = a2; hreg0[j * 4 + 3] = a3;
        unsigned hw, lw_;
        splitf2(a0, a1, hw, lw_); h0hi[r0 * HWU + ad] = hw; h0lo[r0 * HWU + ad] = lw_;
        splitf2(a2, a3, hw, lw_); h0hi[(r0 + 8) * HWU + ad] = hw; h0lo[(r0 + 8) * HWU + ad] = lw_;
        float b0 = g_fcdec[131072 + (bg + r0) * 256 + cb];
        float b1 = g_fcdec[131072 + (bg + r0) * 256 + cb + 1];
        float b2 = g_fcdec[131072 + (bg + r0 + 8) * 256 + cb];
        float b3 = g_fcdec[131072 + (bg + r0 + 8) * 256 + cb + 1];
        hreg1[j * 4 + 0] = b0; hreg1[j * 4 + 1] = b1;
        hreg1[j * 4 + 2] = b2; hreg1[j * 4 + 3] = b3;
        splitf2(b0, b1, hw, lw_); h1hi[r0 * HWU + ad] = hw; h1lo[r0 * HWU + ad] = lw_;
        splitf2(b2, b3, hw, lw_); h1hi[(r0 + 8) * HWU + ad] = hw; h1lo[(r0 + 8) * HWU + ad] = lw_;
    }
    if (tid < 32) ys[tid] = 0.f;
    __syncthreads();

    const unsigned* P3 = g_pack + 3 * PACK_PER_MAT;   // dec_Whh0
    const unsigned* P4 = g_pack + 4 * PACK_PER_MAT;   // dec_Wih1
    const unsigned* P5 = g_pack + 5 * PACK_PER_MAT;   // dec_Whh1

    for (int t = 0; t < T_LEN; t++) {
        float Cr[4][4], Cz[4][4], Cin[4][4], Chn[4][4];
        // ---- layer 0 (input = previous y, 2-dim) ----
        init_gates(Cr, Cz, Cin, Chn, bih0, bhh0, w, q);
        add_x2(Cr, Cz, Cin, Wih0, ys[r0 * 2], ys[r0 * 2 + 1],
               ys[(r0 + 8) * 2], ys[(r0 + 8) * 2 + 1], w, q);
        gemm_acc(h0hi, h0lo, P3, Cr, Cz, Chn, w, lane);
        __syncthreads();
        combine_reg(hreg0, h0hi, h0lo, Cr, Cz, Cin, Chn, w, r0, q, nullptr);
        __syncthreads();
        // ---- layer 1 ----
        init_gates(Cr, Cz, Cin, Chn, bih1, bhh1, w, q);
        gemm_acc(h0hi, h0lo, P4, Cr, Cz, Cin, w, lane);
        gemm_acc(h1hi, h1lo, P5, Cr, Cz, Chn, w, lane);
        __syncthreads();
        combine_reg(hreg1, h1hi, h1lo, Cr, Cz, Cin, Chn, w, r0, q, h1f);
        __syncthreads();
        // ---- fc_out: y = h1 @ W^T + b  (32 outputs, 8 threads each) ----
        {
            int oi = tid >> 3, part = tid & 7;
            int row = oi >> 1, od = oi & 1;
            const float* hr = h1f + row * HS + part * 32;
            const float* wr = fco_w + od * 256 + part * 32;
            float sum = 0.f;
#pragma unroll 8
            for (int k = 0; k < 32; k++) sum += hr[k] * wr[k];
            sum += __shfl_down_sync(0xffffffffu, sum, 4);
            sum += __shfl_down_sync(0xffffffffu, sum, 2);
            sum += __shfl_down_sync(0xffffffffu, sum, 1);
            if (part == 0) {
                float val = sum + fco_b[od];
                out[(bg + row) * 360 + t * 2 + od] = val;
                ys[row * 2 + od] = val;
            }
        }
        __syncthreads();
    }
}

// ---------------------------------------------------------------------------
#define ENC_SMEM 60160
#define DEC_SMEM 51840

extern "C" void kernel_launch(void* const* d_in, const int* in_sizes, int n_in,
                              void* d_out, int out_size) {
    const float* x        = (const float*)d_in[0];
    const float* ln_w     = (const float*)d_in[1];
    const float* ln_b     = (const float*)d_in[2];
    const float* enc_Wih0 = (const float*)d_in[3];
    const float* enc_Whh0 = (const float*)d_in[4];
    const float* enc_bih0 = (const float*)d_in[5];
    const float* enc_bhh0 = (const float*)d_in[6];
    const float* enc_Wih1 = (const float*)d_in[7];
    const float* enc_Whh1 = (const float*)d_in[8];
    const float* enc_bih1 = (const float*)d_in[9];
    const float* enc_bhh1 = (const float*)d_in[10];
    const float* dec_Wih0 = (const float*)d_in[11];
    const float* dec_Whh0 = (const float*)d_in[12];
    const float* dec_bih0 = (const float*)d_in[13];
    const float* dec_bhh0 = (const float*)d_in[14];
    const float* dec_Wih1 = (const float*)d_in[15];
    const float* dec_Whh1 = (const float*)d_in[16];
    const float* dec_bih1 = (const float*)d_in[17];
    const float* dec_bhh1 = (const float*)d_in[18];
    const float* fc_enc_w = (const float*)d_in[19];
    const float* fc_enc_b = (const float*)d_in[20];
    const float* fc_dec_w = (const float*)d_in[21];
    const float* fc_dec_b = (const float*)d_in[22];
    const float* fc_out_w = (const float*)d_in[23];
    const float* fc_out_b = (const float*)d_in[24];
    float* out = (float*)d_out;

    static int attr_done = 0;
    if (!attr_done) {
        cudaFuncSetAttribute(enc_kernel, cudaFuncAttributeMaxDynamicSharedMemorySize, ENC_SMEM);
        cudaFuncSetAttribute(dec_kernel, cudaFuncAttributeMaxDynamicSharedMemorySize, DEC_SMEM);
        attr_done = 1;
    }

    pack_kernel<<<1152, 256>>>(enc_Whh0, enc_Wih1, enc_Whh1,
                               dec_Whh0, dec_Wih1, dec_Whh1);
    ln_kernel<<<512, 128>>>(x, ln_w, ln_b);
    enc_kernel<<<32, 256, ENC_SMEM>>>(enc_Wih0, enc_bih0, enc_bhh0, enc_bih1, enc_bhh1,
                                      fc_enc_w, fc_enc_b, fc_dec_w, fc_dec_b, out);
    dec_kernel<<<32, 256, DEC_SMEM>>>(dec_Wih0, dec_bih0, dec_bhh0, dec_bih1, dec_bhh1,
                                      fc_out_w, fc_out_b, out);
}

// round 16
// speedup vs baseline: 1.0012x; 1.0012x over previous
#include <cuda_runtime.h>
#include <cuda_bf16.h>
#include <cstdint>

// ---------------------------------------------------------------------------
// RNN Autoencoder (GRU enc/dec), B=512, T=180, H=256, LAT=128
//   32 blocks x 512 threads (16 warps), 16 batch rows per block.
//   Each warp owns 16 h-columns -> small accumulators, no register spills.
//   bf16 hi/lo split tensor-core GEMMs (3 mma products per tile).
//   h state kept PRE-SPLIT (bf16 hi/lo u32) in smem; fp32 h in regs.
// ---------------------------------------------------------------------------

#define T_LEN 180
#define HID   256
#define BT    16
#define HS    264               // fp32 h1 stride (floats)
#define HWU   136               // hi/lo row stride in u32 (128 + 8)
#define PACK_PER_MAT 196608     // 96 ntiles * 16 ktiles * 32 lanes * 4 u32
#define RECON_ELEMS  (512 * T_LEN * 2)   // 184320
#define NT 512                  // threads per block

__device__ __align__(16) unsigned g_pack[6 * PACK_PER_MAT]; // packed weights
__device__ float g_xn[512 * T_LEN * 2];                      // layernormed input
__device__ float g_fcdec[512 * 512];                         // fc_dec output flat

// ---------------------------------------------------------------------------
__device__ __forceinline__ float sigm(float x) {
    return __fdividef(1.f, 1.f + __expf(-x));
}
__device__ __forceinline__ float tanh_(float x) {
    float ax = fabsf(x);
    float e  = __expf(-2.f * ax);
    float t  = __fdividef(1.f - e, 1.f + e);
    return copysignf(t, x);
}

// split floats (x,y) into bf16 hi pair and bf16 residual-lo pair (packed bf16x2)
__device__ __forceinline__ void splitf2(float x, float y, unsigned& hi, unsigned& lo) {
    __nv_bfloat16 hx = __float2bfloat16(x);
    __nv_bfloat16 hy = __float2bfloat16(y);
    __nv_bfloat16 lx = __float2bfloat16(x - __bfloat162float(hx));
    __nv_bfloat16 ly = __float2bfloat16(y - __bfloat162float(hy));
    hi = ((unsigned)__bfloat16_as_ushort(hy) << 16) | (unsigned)__bfloat16_as_ushort(hx);
    lo = ((unsigned)__bfloat16_as_ushort(ly) << 16) | (unsigned)__bfloat16_as_ushort(lx);
}

__device__ __forceinline__ void mma16816(float* c, const unsigned* a, unsigned b0, unsigned b1) {
    asm volatile(
        "mma.sync.aligned.m16n8k16.row.col.f32.bf16.bf16.f32 "
        "{%0,%1,%2,%3},{%4,%5,%6,%7},{%8,%9},{%0,%1,%2,%3};\n"
        : "+f"(c[0]), "+f"(c[1]), "+f"(c[2]), "+f"(c[3])
        : "r"(a[0]), "r"(a[1]), "r"(a[2]), "r"(a[3]), "r"(b0), "r"(b1));
}

// hi/lo smem pair layout: pair-col c (0..127, covers h cols 2c,2c+1)
//   u32 addr(row,c) = row*HWU + (c>>3)*8 + (c&3)*2 + ((c>>2)&1)
// gemm A-frag pair (c0, c0+4), c0 = 8*kt+q -> two adjacent u32 -> LDS.64
__device__ __forceinline__ int pair_addr(int c) {
    return (c >> 3) * 8 + (c & 3) * 2 + ((c >> 2) & 1);
}

// ---------------------------------------------------------------------------
// pack: W (768x256 row-major) -> per-lane B-fragment order with hi/lo split.
//   u32 offset = m*PACK_PER_MAT + nt*2048 + kt*128 + lane*4
// ---------------------------------------------------------------------------
__global__ void pack_kernel(const float* __restrict__ w0, const float* __restrict__ w1,
                            const float* __restrict__ w2, const float* __restrict__ w3,
                            const float* __restrict__ w4, const float* __restrict__ w5) {
    int tid = blockIdx.x * blockDim.x + threadIdx.x;
    if (tid >= 6 * 49152) return;
    int m   = tid / 49152;
    int rem = tid % 49152;
    int nt  = rem >> 9;
    int kt  = (rem >> 5) & 15;
    int t   = rem & 31;
    const float* W = (m == 0) ? w0 : (m == 1) ? w1 : (m == 2) ? w2
                   : (m == 3) ? w3 : (m == 4) ? w4 : w5;
    int n  = nt * 8 + (t >> 2);
    int k0 = kt * 16 + (t & 3) * 2;
    const float* row = W + n * HID;
    unsigned h0, l0, h1, l1;
    splitf2(row[k0],     row[k0 + 1], h0, l0);
    splitf2(row[k0 + 8], row[k0 + 9], h1, l1);
    unsigned* dst = g_pack + m * PACK_PER_MAT + (((nt * 16 + kt) * 32 + t) << 2);
    uint4 v; v.x = h0; v.y = h1; v.z = l0; v.w = l1;
    *(uint4*)dst = v;
}

// ---------------------------------------------------------------------------
__global__ void ln_kernel(const float* __restrict__ x, const float* __restrict__ lw,
                          const float* __restrict__ lb) {
    int b = blockIdx.x;
    const float* xb = x + b * 360;
    float s = 0.f, s2 = 0.f;
    for (int i = threadIdx.x; i < 360; i += blockDim.x) {
        float v = xb[i]; s += v; s2 += v * v;
    }
    __shared__ float sh[8];
    for (int o = 16; o; o >>= 1) {
        s  += __shfl_down_sync(0xffffffffu, s, o);
        s2 += __shfl_down_sync(0xffffffffu, s2, o);
    }
    int wid = threadIdx.x >> 5;
    if ((threadIdx.x & 31) == 0) { sh[wid] = s; sh[4 + wid] = s2; }
    __syncthreads();
    if (threadIdx.x == 0) {
        float ts = sh[0] + sh[1] + sh[2] + sh[3];
        float t2 = sh[4] + sh[5] + sh[6] + sh[7];
        float mu = ts * (1.f / 360.f);
        float var = t2 * (1.f / 360.f) - mu * mu;
        sh[0] = mu;
        sh[1] = rsqrtf(var + 1e-5f);
    }
    __syncthreads();
    float mu = sh[0], rstd = sh[1];
    for (int i = threadIdx.x; i < 360; i += blockDim.x)
        g_xn[b * 360 + i] = (xb[i] - mu) * rstd * lw[i] + lb[i];
}

// ---------------------------------------------------------------------------
// warp-GEMM: accumulate (16 x 256 pre-split smem) @ W^T slice into gate accums
// warp w (0..15) owns h-cols [16w,16w+16) -> ntiles per gate {2w, 2w+1}
// ---------------------------------------------------------------------------
__device__ __forceinline__ void gemm_acc(const unsigned* __restrict__ hi,
                                         const unsigned* __restrict__ lo,
                                         const unsigned* __restrict__ P,
                                         float Cr[2][4], float Cz[2][4], float Cn[2][4],
                                         int w, int lane) {
    const int r0 = lane >> 2, q = lane & 3;
    const unsigned* hA = hi + r0 * HWU;
    const unsigned* hB = hi + (r0 + 8) * HWU;
    const unsigned* lA = lo + r0 * HWU;
    const unsigned* lB = lo + (r0 + 8) * HWU;
    const unsigned* Pl = P + lane * 4 + (unsigned)(w * 2) * 2048u;
#pragma unroll 4
    for (int kt = 0; kt < 16; kt++) {
        const int off = kt * 8 + q * 2;
        unsigned ah[4], al[4];
        uint2 t0 = *(const uint2*)(hA + off); ah[0] = t0.x; ah[2] = t0.y;
        uint2 t1 = *(const uint2*)(hB + off); ah[1] = t1.x; ah[3] = t1.y;
        uint2 t2 = *(const uint2*)(lA + off); al[0] = t2.x; al[2] = t2.y;
        uint2 t3 = *(const uint2*)(lB + off); al[1] = t3.x; al[3] = t3.y;
        const unsigned* pk = Pl + kt * 128;
#pragma unroll
        for (int j = 0; j < 2; j++) {
            uint4 Br = *(const uint4*)(pk + (unsigned)j * 2048u);
            uint4 Bz = *(const uint4*)(pk + (unsigned)(j + 32) * 2048u);
            uint4 Bn = *(const uint4*)(pk + (unsigned)(j + 64) * 2048u);
            mma16816(Cr[j], ah, Br.x, Br.y);
            mma16816(Cz[j], ah, Bz.x, Bz.y);
            mma16816(Cn[j], ah, Bn.x, Bn.y);
            mma16816(Cr[j], ah, Br.z, Br.w);
            mma16816(Cz[j], ah, Bz.z, Bz.w);
            mma16816(Cn[j], ah, Bn.z, Bn.w);
            mma16816(Cr[j], al, Br.x, Br.y);
            mma16816(Cz[j], al, Bz.x, Bz.y);
            mma16816(Cn[j], al, Bn.x, Bn.y);
        }
    }
}

// ---------------------------------------------------------------------------
__device__ __forceinline__ void init_gates(float Cr[2][4], float Cz[2][4],
                                           float Cin[2][4], float Chn[2][4],
                                           const float* __restrict__ bih,
                                           const float* __restrict__ bhh, int w, int q) {
#pragma unroll
    for (int j = 0; j < 2; j++) {
        int cb = 16 * w + 8 * j + 2 * q;
        float2 bi, bh;
        bi = *(const float2*)(bih + cb); bh = *(const float2*)(bhh + cb);
        Cr[j][0] = Cr[j][2] = bi.x + bh.x; Cr[j][1] = Cr[j][3] = bi.y + bh.y;
        bi = *(const float2*)(bih + 256 + cb); bh = *(const float2*)(bhh + 256 + cb);
        Cz[j][0] = Cz[j][2] = bi.x + bh.x; Cz[j][1] = Cz[j][3] = bi.y + bh.y;
        bi = *(const float2*)(bih + 512 + cb); bh = *(const float2*)(bhh + 512 + cb);
        Cin[j][0] = Cin[j][2] = bi.x; Cin[j][1] = Cin[j][3] = bi.y;
        Chn[j][0] = Chn[j][2] = bh.x; Chn[j][1] = Chn[j][3] = bh.y;
    }
}

// scalar ih path for 2-dim inputs: Wih is (768,2) row-major
__device__ __forceinline__ void add_x2(float Cr[2][4], float Cz[2][4], float Cin[2][4],
                                       const float* __restrict__ Wih,
                                       float xa0, float xa1, float xb0, float xb1,
                                       int w, int q) {
#pragma unroll
    for (int j = 0; j < 2; j++) {
        int cb = 16 * w + 8 * j + 2 * q;
#pragma unroll
        for (int g = 0; g < 3; g++) {
            float* C = (g == 0) ? Cr[j] : (g == 1) ? Cz[j] : Cin[j];
            int c0 = g * 256 + cb;
            float2 w0 = *(const float2*)(Wih + c0 * 2);
            float2 w1 = *(const float2*)(Wih + (c0 + 1) * 2);
            C[0] += xa0 * w0.x + xa1 * w0.y;
            C[1] += xa0 * w1.x + xa1 * w1.y;
            C[2] += xb0 * w0.x + xb1 * w0.y;
            C[3] += xb0 * w1.x + xb1 * w1.y;
        }
    }
}

// GRU gate combine: h_prev in regs, write new h to regs + hi/lo smem (+opt fp32)
__device__ __forceinline__ void combine_reg(float* __restrict__ hreg,
                                            unsigned* __restrict__ hi, unsigned* __restrict__ lo,
                                            float Cr[2][4], float Cz[2][4],
                                            float Cin[2][4], float Chn[2][4],
                                            int w, int r0, int q, float* __restrict__ f32s) {
#pragma unroll
    for (int j = 0; j < 2; j++) {
        int cb = 16 * w + 8 * j + 2 * q;
        float nh[4];
#pragma unroll
        for (int k = 0; k < 4; k++) {
            float rg = sigm(Cr[j][k]);
            float zg = sigm(Cz[j][k]);
            float ng = tanh_(Cin[j][k] + rg * Chn[j][k]);
            nh[k] = (1.f - zg) * ng + zg * hreg[j * 4 + k];
            hreg[j * 4 + k] = nh[k];
        }
        int ad = pair_addr(cb >> 1);
        unsigned hw, lw_;
        splitf2(nh[0], nh[1], hw, lw_);
        hi[r0 * HWU + ad] = hw; lo[r0 * HWU + ad] = lw_;
        splitf2(nh[2], nh[3], hw, lw_);
        hi[(r0 + 8) * HWU + ad] = hw; lo[(r0 + 8) * HWU + ad] = lw_;
        if (f32s) {
            *(float2*)(f32s + r0 * HS + cb)       = make_float2(nh[0], nh[1]);
            *(float2*)(f32s + (r0 + 8) * HS + cb) = make_float2(nh[2], nh[3]);
        }
    }
}

// ---------------------------------------------------------------------------
// encoder: 2-layer GRU scan + fc_enc (-> z output) + fc_dec (-> g_fcdec)
// dyn smem: h0hi(2176u) h0lo h1hi h1lo | h1f(4224f) | zs(2112f) = 60160B
// ---------------------------------------------------------------------------
__global__ void __launch_bounds__(NT, 1) enc_kernel(
    const float* __restrict__ Wih0, const float* __restrict__ bih0,
    const float* __restrict__ bhh0, const float* __restrict__ bih1,
    const float* __restrict__ bhh1,
    const float* __restrict__ fce_w, const float* __restrict__ fce_b,
    const float* __restrict__ fcd_w, const float* __restrict__ fcd_b,
    float* __restrict__ out) {
    extern __shared__ unsigned dsm[];
    unsigned* h0hi = dsm;
    unsigned* h0lo = dsm + 2176;
    unsigned* h1hi = dsm + 4352;
    unsigned* h1lo = dsm + 6528;
    float* h1f = (float*)(dsm + 8704);
    float* zs  = h1f + 4224;

    const int tid = threadIdx.x;
    const int w = tid >> 5, lane = tid & 31;
    const int r0 = lane >> 2, q = lane & 3;
    const int bg = blockIdx.x * BT;

    for (int i = tid; i < 8704; i += NT) dsm[i] = 0;
    float hreg0[8], hreg1[8];
#pragma unroll
    for (int k = 0; k < 8; k++) { hreg0[k] = 0.f; hreg1[k] = 0.f; }
    __syncthreads();

    const unsigned* P0 = g_pack;                      // enc_Whh0
    const unsigned* P1 = g_pack + PACK_PER_MAT;       // enc_Wih1
    const unsigned* P2 = g_pack + 2 * PACK_PER_MAT;   // enc_Whh1

    for (int t = 0; t < T_LEN; t++) {
        float Cr[2][4], Cz[2][4], Cin[2][4], Chn[2][4];
        // ---- layer 0 ----
        init_gates(Cr, Cz, Cin, Chn, bih0, bhh0, w, q);
        {
            const float* xr = g_xn + (bg + r0) * 360 + t * 2;
            const float* xs = g_xn + (bg + r0 + 8) * 360 + t * 2;
            add_x2(Cr, Cz, Cin, Wih0, xr[0], xr[1], xs[0], xs[1], w, q);
        }
        gemm_acc(h0hi, h0lo, P0, Cr, Cz, Chn, w, lane);
        __syncthreads();
        combine_reg(hreg0, h0hi, h0lo, Cr, Cz, Cin, Chn, w, r0, q, nullptr);
        __syncthreads();
        // ---- layer 1 ----
        init_gates(Cr, Cz, Cin, Chn, bih1, bhh1, w, q);
        gemm_acc(h0hi, h0lo, P1, Cr, Cz, Cin, w, lane);  // ih side
        gemm_acc(h1hi, h1lo, P2, Cr, Cz, Chn, w, lane);  // hh side
        __syncthreads();
        combine_reg(hreg1, h1hi, h1lo, Cr, Cz, Cin, Chn, w, r0, q, h1f);
        __syncthreads();
    }

    // ---- fc_enc: z = tanh(h1 @ W^T + b) ; write z to output tail ----
    for (int o = tid; o < 16 * 128; o += NT) {
        int row = o >> 7, lat = o & 127;
        float sum = fce_b[lat];
        const float* wr = fce_w + lat * 256;
        const float* hr = h1f + row * HS;
        for (int k = 0; k < 256; k++) sum += hr[k] * wr[k];
        float zv = tanh_(sum);
        zs[row * 132 + lat] = zv;
        out[RECON_ELEMS + (bg + row) * 128 + lat] = zv;
    }
    __syncthreads();

    // ---- fc_dec: (16 x 128) @ (128 -> 512) -> g_fcdec flat ----
    for (int o = tid; o < 16 * 512; o += NT) {
        int row = o >> 9, c = o & 511;
        float sum = fcd_b[c];
        const float* wr = fcd_w + c * 128;
        const float* zr = zs + row * 132;
        for (int k = 0; k < 128; k++) sum += zr[k] * wr[k];
        g_fcdec[(bg + row) * 512 + c] = sum;
    }
}

// ---------------------------------------------------------------------------
// decoder: autoregressive 2-layer GRU + fc_out each step
// dyn smem: h0hi h0lo h1hi h1lo | h1f | ys(32f) = 51840B
// ---------------------------------------------------------------------------
__global__ void __launch_bounds__(NT, 1) dec_kernel(
    const float* __restrict__ Wih0, const float* __restrict__ bih0,
    const float* __restrict__ bhh0, const float* __restrict__ bih1,
    const float* __restrict__ bhh1,
    const float* __restrict__ fco_w, const float* __restrict__ fco_b,
    float* __restrict__ out) {
    extern __shared__ unsigned dsm[];
    unsigned* h0hi = dsm;
    unsigned* h0lo = dsm + 2176;
    unsigned* h1hi = dsm + 4352;
    unsigned* h1lo = dsm + 6528;
    float* h1f = (float*)(dsm + 8704);
    float* ys  = h1f + 4224;

    const int tid = threadIdx.x;
    const int w = tid >> 5, lane = tid & 31;
    const int r0 = lane >> 2, q = lane & 3;
    const int bg = blockIdx.x * BT;

    // init hidden state from g_fcdec via raw reshape(NL,B,H) view
    float hreg0[8], hreg1[8];
#pragma unroll
    for (int j = 0; j < 2; j++) {
        int cb = 16 * w + 8 * j + 2 * q;
        int ad = pair_addr(cb >> 1);
        float a0 = g_fcdec[(bg + r0) * 256 + cb];
        float a1 = g_fcdec[(bg + r0) * 256 + cb + 1];
        float a2 = g_fcdec[(bg + r0 + 8) * 256 + cb];
        float a3 = g_fcdec[(bg + r0 + 8) * 256 + cb + 1];
        hreg0[j * 4 + 0] = a0; hreg0[j * 4 + 1] = a1;
        hreg0[j * 4 + 2] = a2; hreg0[j * 4 + 3] = a3;
        unsigned hw, lw_;
        splitf2(a0, a1, hw, lw_); h0hi[r0 * HWU + ad] = hw; h0lo[r0 * HWU + ad] = lw_;
        splitf2(a2, a3, hw, lw_); h0hi[(r0 + 8) * HWU + ad] = hw; h0lo[(r0 + 8) * HWU + ad] = lw_;
        float b0 = g_fcdec[131072 + (bg + r0) * 256 + cb];
        float b1 = g_fcdec[131072 + (bg + r0) * 256 + cb + 1];
        float b2 = g_fcdec[131072 + (bg + r0 + 8) * 256 + cb];
        float b3 = g_fcdec[131072 + (bg + r0 + 8) * 256 + cb + 1];
        hreg1[j * 4 + 0] = b0; hreg1[j * 4 + 1] = b1;
        hreg1[j * 4 + 2] = b2; hreg1[j * 4 + 3] = b3;
        splitf2(b0, b1, hw, lw_); h1hi[r0 * HWU + ad] = hw; h1lo[r0 * HWU + ad] = lw_;
        splitf2(b2, b3, hw, lw_); h1hi[(r0 + 8) * HWU + ad] = hw; h1lo[(r0 + 8) * HWU + ad] = lw_;
    }
    if (tid < 32) ys[tid] = 0.f;
    __syncthreads();

    const unsigned* P3 = g_pack + 3 * PACK_PER_MAT;   // dec_Whh0
    const unsigned* P4 = g_pack + 4 * PACK_PER_MAT;   // dec_Wih1
    const unsigned* P5 = g_pack + 5 * PACK_PER_MAT;   // dec_Whh1

    for (int t = 0; t < T_LEN; t++) {
        float Cr[2][4], Cz[2][4], Cin[2][4], Chn[2][4];
        // ---- layer 0 (input = previous y, 2-dim) ----
        init_gates(Cr, Cz, Cin, Chn, bih0, bhh0, w, q);
        add_x2(Cr, Cz, Cin, Wih0, ys[r0 * 2], ys[r0 * 2 + 1],
               ys[(r0 + 8) * 2], ys[(r0 + 8) * 2 + 1], w, q);
        gemm_acc(h0hi, h0lo, P3, Cr, Cz, Chn, w, lane);
        __syncthreads();
        combine_reg(hreg0, h0hi, h0lo, Cr, Cz, Cin, Chn, w, r0, q, nullptr);
        __syncthreads();
        // ---- layer 1 ----
        init_gates(Cr, Cz, Cin, Chn, bih1, bhh1, w, q);
        gemm_acc(h0hi, h0lo, P4, Cr, Cz, Cin, w, lane);
        gemm_acc(h1hi, h1lo, P5, Cr, Cz, Chn, w, lane);
        __syncthreads();
        combine_reg(hreg1, h1hi, h1lo, Cr, Cz, Cin, Chn, w, r0, q, h1f);
        __syncthreads();
        // ---- fc_out: y = h1 @ W^T + b  (32 outputs, 16 threads each) ----
        {
            int oi = tid >> 4, part = tid & 15;
            int row = oi >> 1, od = oi & 1;
            const float* hr = h1f + row * HS + part * 16;
            const float* wr = fco_w + od * 256 + part * 16;
            float sum = 0.f;
#pragma unroll
            for (int k = 0; k < 16; k++) sum += hr[k] * wr[k];
            sum += __shfl_down_sync(0xffffffffu, sum, 8, 16);
            sum += __shfl_down_sync(0xffffffffu, sum, 4, 16);
            sum += __shfl_down_sync(0xffffffffu, sum, 2, 16);
            sum += __shfl_down_sync(0xffffffffu, sum, 1, 16);
            if (part == 0) {
                float val = sum + fco_b[od];
                out[(bg + row) * 360 + t * 2 + od] = val;
                ys[row * 2 + od] = val;
            }
        }
        __syncthreads();
    }
}

// ---------------------------------------------------------------------------
#define ENC_SMEM 60160
#define DEC_SMEM 51840

extern "C" void kernel_launch(void* const* d_in, const int* in_sizes, int n_in,
                              void* d_out, int out_size) {
    const float* x        = (const float*)d_in[0];
    const float* ln_w     = (const float*)d_in[1];
    const float* ln_b     = (const float*)d_in[2];
    const float* enc_Wih0 = (const float*)d_in[3];
    const float* enc_Whh0 = (const float*)d_in[4];
    const float* enc_bih0 = (const float*)d_in[5];
    const float* enc_bhh0 = (const float*)d_in[6];
    const float* enc_Wih1 = (const float*)d_in[7];
    const float* enc_Whh1 = (const float*)d_in[8];
    const float* enc_bih1 = (const float*)d_in[9];
    const float* enc_bhh1 = (const float*)d_in[10];
    const float* dec_Wih0 = (const float*)d_in[11];
    const float* dec_Whh0 = (const float*)d_in[12];
    const float* dec_bih0 = (const float*)d_in[13];
    const float* dec_bhh0 = (const float*)d_in[14];
    const float* dec_Wih1 = (const float*)d_in[15];
    const float* dec_Whh1 = (const float*)d_in[16];
    const float* dec_bih1 = (const float*)d_in[17];
    const float* dec_bhh1 = (const float*)d_in[18];
    const float* fc_enc_w = (const float*)d_in[19];
    const float* fc_enc_b = (const float*)d_in[20];
    const float* fc_dec_w = (const float*)d_in[21];
    const float* fc_dec_b = (const float*)d_in[22];
    const float* fc_out_w = (const float*)d_in[23];
    const float* fc_out_b = (const float*)d_in[24];
    float* out = (float*)d_out;

    static int attr_done = 0;
    if (!attr_done) {
        cudaFuncSetAttribute(enc_kernel, cudaFuncAttributeMaxDynamicSharedMemorySize, ENC_SMEM);
        cudaFuncSetAttribute(dec_kernel, cudaFuncAttributeMaxDynamicSharedMemorySize, DEC_SMEM);
        attr_done = 1;
    }

    pack_kernel<<<1152, 256>>>(enc_Whh0, enc_Wih1, enc_Whh1,
                               dec_Whh0, dec_Wih1, dec_Whh1);
    ln_kernel<<<512, 128>>>(x, ln_w, ln_b);
    enc_kernel<<<32, NT, ENC_SMEM>>>(enc_Wih0, enc_bih0, enc_bhh0, enc_bih1, enc_bhh1,
                                     fc_enc_w, fc_enc_b, fc_dec_w, fc_dec_b, out);
    dec_kernel<<<32, NT, DEC_SMEM>>>(dec_Wih0, dec_bih0, dec_bhh0, dec_bih1, dec_bhh1,
                                     fc_out_w, fc_out_b, out);
}